// round 6
// baseline (speedup 1.0000x reference)
#include <cuda_runtime.h>
#include <cuda_bf16.h>
#include <stdint.h>

// Problem constants
#define BB   4
#define H    352
#define W    1216
#define HW   (H*W)               // 428032
#define NPX  (BB*HW)             // 1712128 pixels
#define PAD  2
#define HP   (H + 2*PAD)         // 356
#define WP   (W + 2*PAD)         // 1220
#define NPAD (BB*HP*WP)          // 1737280 < 2^21
#define PROP 18

// Packed tap record (u64):
//  [0,21)   : padded linear index of top-left corner
//  [21,34)  : fy  (13-bit fraction, /8192)
//  [34,47)  : fx  (13-bit fraction, /8192)
//  [47,64)  : aff (17-bit fixed point, (q-65536)/32768)
// Stored as 4 planes of uint4 (two taps per 16B record) for LDG.128.

// Pair-duplicated feat buffers: elem [y][x] = (f[y,x], f[y,x+1]).
// A bilinear corner pair = one aligned 8B load.
__device__ float2 g_buf[2][NPAD];
__device__ uint4  d_meta[4 * NPX];

// ---------------------------------------------------------------------------
__global__ void zero_kernel() {
    int i = blockIdx.x * blockDim.x + threadIdx.x;
    if (i < 4 * NPAD) ((float*)&g_buf[0][0])[i] = 0.0f;
}

__global__ void init_kernel(const float* __restrict__ feat,
                            const float* __restrict__ conf) {
    int p = blockIdx.x * blockDim.x + threadIdx.x;
    if (p >= NPX) return;
    int b = p / HW;
    int r = p - b * HW;
    int y = r / W;
    int x = r - y * W;
    int pidx = (b * HP + y + PAD) * WP + (x + PAD);
    float v = feat[p] * conf[p];
    float* base = (float*)&g_buf[0][0];
    base[2 * pidx]             = v;   // [pidx].x
    base[2 * (pidx - 1) + 1]   = v;   // [pidx-1].y
}

// ---------------------------------------------------------------------------
__device__ __forceinline__ unsigned long long encode_tap(
        int b, int y, int x, int j, float dy, float dx, float aff)
{
    float ys = (float)(y + j / 3 - 1) + dy;
    float xs = (float)(x + j % 3 - 1) + dx;
    float y0f = floorf(ys);
    float x0f = floorf(xs);
    float fy = ys - y0f;
    float fx = xs - x0f;
    int iy = (int)fmaxf(fminf(y0f, 1.0e6f), -1.0e6f);
    int ix = (int)fmaxf(fminf(x0f, 1.0e6f), -1.0e6f);
    // clamp into padded box; out-of-image corners land on guaranteed zeros
    int yp = min(max(iy + PAD, 0), HP - 2);
    int xp = min(max(ix + PAD, 0), WP - 2);
    unsigned long long idx = (unsigned long long)((b * HP + yp) * WP + xp);
    int fu = (int)(fy * 8192.0f + 0.5f); fu = min(max(fu, 0), 8191);
    int fv = (int)(fx * 8192.0f + 0.5f); fv = min(max(fv, 0), 8191);
    int qa = (int)floorf(aff * 32768.0f + 0.5f) + 65536;
    qa = min(max(qa, 0), 131071);
    return idx | ((unsigned long long)fu << 21)
               | ((unsigned long long)fv << 34)
               | ((unsigned long long)qa << 47);
}

__device__ __forceinline__ void write_meta(int p, int b, int y, int x,
                                           const float* acc, float inv_scale) {
    float a[8];
    float s = 0.0f;
#pragma unroll
    for (int k = 0; k < 8; k++) {
        a[k] = tanhf(acc[16 + k]) * inv_scale;
        s += fabsf(a[k]);
    }
    s += 1e-4f;
    if (s < 1.0f) s = 1.0f;
    float invs = 1.0f / s;
#pragma unroll
    for (int k = 0; k < 8; k++) a[k] *= invs;

    unsigned long long rec[8];
#pragma unroll
    for (int j = 0; j < 9; j++) {
        if (j == 4) continue;
        int k = (j < 4) ? j : j - 1;
        rec[k] = encode_tap(b, y, x, j, acc[2 * k], acc[2 * k + 1], a[k]);
    }
#pragma unroll
    for (int q = 0; q < 4; q++) {
        unsigned long long m0 = rec[2 * q], m1 = rec[2 * q + 1];
        d_meta[q * NPX + p] = make_uint4((unsigned)m0, (unsigned)(m0 >> 32),
                                         (unsigned)m1, (unsigned)(m1 >> 32));
    }
}

__global__ void conv_meta_kernel(const float* __restrict__ guid,
                                 const float* __restrict__ w_oa,
                                 const float* __restrict__ b_oa,
                                 const float* __restrict__ aff_scale) {
    __shared__ float ws[1728];
    __shared__ float bs[24];
    for (int i = threadIdx.x; i < 1728; i += blockDim.x) ws[i] = w_oa[i];
    if (threadIdx.x < 24) bs[threadIdx.x] = b_oa[threadIdx.x];
    __syncthreads();

    int t  = blockIdx.x * blockDim.x + threadIdx.x;
    int p0 = 2 * t;
    if (p0 >= NPX) return;
    int b = p0 / HW;
    int r = p0 - b * HW;
    int y = r / W;
    int x = r - y * W;   // x even; x+1 in same row (W even)

    float acc0[24], acc1[24];
#pragma unroll
    for (int c = 0; c < 24; c++) { acc0[c] = bs[c]; acc1[c] = bs[c]; }

    const float* gb = guid + (size_t)b * 8 * HW;
    for (int i = 0; i < 8; i++) {
        const float* gch = gb + i * HW;
#pragma unroll
        for (int u = 0; u < 3; u++) {
            int yy = y + u - 1;
            bool yv = (yy >= 0) && (yy < H);
            const float* grow = gch + yy * W;
            float v[4];
#pragma unroll
            for (int q = 0; q < 4; q++) {
                int xx = x + q - 1;
                v[q] = (yv && xx >= 0 && xx < W) ? grow[xx] : 0.0f;
            }
#pragma unroll
            for (int kx = 0; kx < 3; kx++) {
#pragma unroll
                for (int c = 0; c < 24; c++) {
                    float w = ws[c * 72 + i * 9 + u * 3 + kx];
                    acc0[c] = fmaf(v[kx],     w, acc0[c]);
                    acc1[c] = fmaf(v[kx + 1], w, acc1[c]);
                }
            }
        }
    }

    float inv_scale = 1.0f / (aff_scale[0] + 1e-8f);
    write_meta(p0,     b, y, x,     acc0, inv_scale);
    write_meta(p0 + 1, b, y, x + 1, acc1, inv_scale);
}

// ---------------------------------------------------------------------------
// One propagation step. Center affinity = 1 - sum(decoded tap affs).
__device__ __forceinline__ void apply_tap(const float2* __restrict__ gin,
                                          unsigned long long m,
                                          float& acc, float& asum) {
    unsigned idx = (unsigned)(m & 0x1FFFFFull);
    float fy = (float)((unsigned)(m >> 21) & 0x1FFFu) * (1.0f / 8192.0f);
    float fx = (float)((unsigned)(m >> 34) & 0x1FFFu) * (1.0f / 8192.0f);
    float av = (float)((int)((unsigned)(m >> 47) & 0x1FFFFu) - 65536)
               * (1.0f / 32768.0f);
    float2 t2 = __ldg(gin + idx);        // (f00, f01) one 8B load
    float2 b2 = __ldg(gin + idx + WP);   // (f10, f11)
    float top = fmaf(fx, t2.y - t2.x, t2.x);
    float bot = fmaf(fx, b2.y - b2.x, b2.x);
    acc  = fmaf(av, fmaf(fy, bot - top, top), acc);
    asum += av;
}

__global__ void iter_kernel(const float* __restrict__ conf,
                            float* __restrict__ out, int sel, int last) {
    int p = blockIdx.x * blockDim.x + threadIdx.x;
    if (p >= NPX) return;
    const float2* __restrict__ gin = g_buf[sel];
    int b = p / HW;
    int r = p - b * HW;
    int y = r / W;
    int x = r - y * W;
    int center = (b * HP + y + PAD) * WP + (x + PAD);

    float acc = 0.0f, asum = 0.0f;
#pragma unroll
    for (int q = 0; q < 4; q++) {
        uint4 mm = d_meta[q * NPX + p];
        unsigned long long m0 = (unsigned long long)mm.x
                              | ((unsigned long long)mm.y << 32);
        unsigned long long m1 = (unsigned long long)mm.z
                              | ((unsigned long long)mm.w << 32);
        apply_tap(gin, m0, acc, asum);
        apply_tap(gin, m1, acc, asum);
    }
    float fc = __ldg(&((const float*)gin)[2 * center]);   // center .x
    float v = fmaf(1.0f - asum, fc, acc);
    if (last) {
        out[p] = v;
    } else {
        float u = conf[p] * v;
        float* base = (float*)&g_buf[sel ^ 1][0];
        base[2 * center]           = u;   // [center].x
        base[2 * (center - 1) + 1] = u;   // [center-1].y
    }
}

// ---------------------------------------------------------------------------
extern "C" void kernel_launch(void* const* d_in, const int* in_sizes, int n_in,
                              void* d_out, int out_size) {
    const float* feat = (const float*)d_in[0];
    const float* guid = (const float*)d_in[1];
    const float* conf = (const float*)d_in[2];
    const float* w    = (const float*)d_in[3];
    const float* bia  = (const float*)d_in[4];
    const float* sc   = (const float*)d_in[5];
    float* out = (float*)d_out;

    const int thr = 256;
    zero_kernel<<<(4 * NPAD + thr - 1) / thr, thr>>>();
    init_kernel<<<(NPX + thr - 1) / thr, thr>>>(feat, conf);
    conv_meta_kernel<<<(NPX / 2 + thr - 1) / thr, thr>>>(guid, w, bia, sc);
    for (int t = 0; t < PROP; t++) {
        iter_kernel<<<(NPX + thr - 1) / thr, thr>>>(conf, out, t & 1, t == PROP - 1);
    }
}

// round 7
// speedup vs baseline: 1.0335x; 1.0335x over previous
#include <cuda_runtime.h>
#include <cuda_bf16.h>
#include <stdint.h>

// Problem constants
#define BB   4
#define H    352
#define W    1216
#define HW   (H*W)               // 428032
#define NPX  (BB*HW)             // 1712128 pixels (even)
#define PAD  2
#define HP   (H + 2*PAD)         // 356
#define WP   (W + 2*PAD)         // 1220
#define NPAD (BB*HP*WP)          // 1737280 < 2^21
#define PROP 18

// Packed tap record (u64):
//  [0,21)   : padded linear index of top-left corner
//  [21,34)  : fy  (13-bit fraction, /8192)
//  [34,47)  : fx  (13-bit fraction, /8192)
//  [47,64)  : aff (17-bit fixed point, (q-65536)/32768)
// Stored as 4 planes of uint4 (two taps per 16B record) for LDG.128.

__device__ float g_buf[2][NPAD];          // scalar padded ping-pong feat (conf-folded)
__device__ uint4 d_meta[4 * NPX];

// ---------------------------------------------------------------------------
__global__ void zero_kernel() {
    int i = blockIdx.x * blockDim.x + threadIdx.x;
    if (i < 2 * NPAD) (&g_buf[0][0])[i] = 0.0f;
}

__global__ void init_kernel(const float* __restrict__ feat,
                            const float* __restrict__ conf) {
    int p = blockIdx.x * blockDim.x + threadIdx.x;
    if (p >= NPX) return;
    int b = p / HW;
    int r = p - b * HW;
    int y = r / W;
    int x = r - y * W;
    int pidx = (b * HP + y + PAD) * WP + (x + PAD);
    g_buf[0][pidx] = feat[p] * conf[p];
}

// ---------------------------------------------------------------------------
__device__ __forceinline__ unsigned long long encode_tap(
        int b, int y, int x, int j, float dy, float dx, float aff)
{
    float ys = (float)(y + j / 3 - 1) + dy;
    float xs = (float)(x + j % 3 - 1) + dx;
    float y0f = floorf(ys);
    float x0f = floorf(xs);
    float fy = ys - y0f;
    float fx = xs - x0f;
    int iy = (int)fmaxf(fminf(y0f, 1.0e6f), -1.0e6f);
    int ix = (int)fmaxf(fminf(x0f, 1.0e6f), -1.0e6f);
    // clamp into padded box; out-of-image corners land on guaranteed zeros
    int yp = min(max(iy + PAD, 0), HP - 2);
    int xp = min(max(ix + PAD, 0), WP - 2);
    unsigned long long idx = (unsigned long long)((b * HP + yp) * WP + xp);
    int fu = (int)(fy * 8192.0f + 0.5f); fu = min(max(fu, 0), 8191);
    int fv = (int)(fx * 8192.0f + 0.5f); fv = min(max(fv, 0), 8191);
    int qa = (int)floorf(aff * 32768.0f + 0.5f) + 65536;
    qa = min(max(qa, 0), 131071);
    return idx | ((unsigned long long)fu << 21)
               | ((unsigned long long)fv << 34)
               | ((unsigned long long)qa << 47);
}

__device__ __forceinline__ void write_meta(int p, int b, int y, int x,
                                           const float* acc, float inv_scale) {
    float a[8];
    float s = 0.0f;
#pragma unroll
    for (int k = 0; k < 8; k++) {
        a[k] = tanhf(acc[16 + k]) * inv_scale;
        s += fabsf(a[k]);
    }
    s += 1e-4f;
    if (s < 1.0f) s = 1.0f;
    float invs = 1.0f / s;
#pragma unroll
    for (int k = 0; k < 8; k++) a[k] *= invs;

    unsigned long long rec[8];
#pragma unroll
    for (int j = 0; j < 9; j++) {
        if (j == 4) continue;
        int k = (j < 4) ? j : j - 1;
        rec[k] = encode_tap(b, y, x, j, acc[2 * k], acc[2 * k + 1], a[k]);
    }
#pragma unroll
    for (int q = 0; q < 4; q++) {
        unsigned long long m0 = rec[2 * q], m1 = rec[2 * q + 1];
        d_meta[q * NPX + p] = make_uint4((unsigned)m0, (unsigned)(m0 >> 32),
                                         (unsigned)m1, (unsigned)(m1 >> 32));
    }
}

__global__ void conv_meta_kernel(const float* __restrict__ guid,
                                 const float* __restrict__ w_oa,
                                 const float* __restrict__ b_oa,
                                 const float* __restrict__ aff_scale) {
    __shared__ float ws[1728];
    __shared__ float bs[24];
    for (int i = threadIdx.x; i < 1728; i += blockDim.x) ws[i] = w_oa[i];
    if (threadIdx.x < 24) bs[threadIdx.x] = b_oa[threadIdx.x];
    __syncthreads();

    int t  = blockIdx.x * blockDim.x + threadIdx.x;
    int p0 = 2 * t;
    if (p0 >= NPX) return;
    int b = p0 / HW;
    int r = p0 - b * HW;
    int y = r / W;
    int x = r - y * W;   // x even; x+1 in same row (W even)

    float acc0[24], acc1[24];
#pragma unroll
    for (int c = 0; c < 24; c++) { acc0[c] = bs[c]; acc1[c] = bs[c]; }

    const float* gb = guid + (size_t)b * 8 * HW;
    for (int i = 0; i < 8; i++) {
        const float* gch = gb + i * HW;
#pragma unroll
        for (int u = 0; u < 3; u++) {
            int yy = y + u - 1;
            bool yv = (yy >= 0) && (yy < H);
            const float* grow = gch + yy * W;
            float v[4];
#pragma unroll
            for (int q = 0; q < 4; q++) {
                int xx = x + q - 1;
                v[q] = (yv && xx >= 0 && xx < W) ? grow[xx] : 0.0f;
            }
#pragma unroll
            for (int kx = 0; kx < 3; kx++) {
#pragma unroll
                for (int c = 0; c < 24; c++) {
                    float w = ws[c * 72 + i * 9 + u * 3 + kx];
                    acc0[c] = fmaf(v[kx],     w, acc0[c]);
                    acc1[c] = fmaf(v[kx + 1], w, acc1[c]);
                }
            }
        }
    }

    float inv_scale = 1.0f / (aff_scale[0] + 1e-8f);
    write_meta(p0,     b, y, x,     acc0, inv_scale);
    write_meta(p0 + 1, b, y, x + 1, acc1, inv_scale);
}

// ---------------------------------------------------------------------------
// One propagation step, 2 pixels per thread. Center affinity = 1 - sum(taps).
__device__ __forceinline__ void apply_tap(const float* __restrict__ gin,
                                          unsigned lo, unsigned hi,
                                          float& acc, float& asum) {
    unsigned long long m = (unsigned long long)lo
                         | ((unsigned long long)hi << 32);
    unsigned idx = (unsigned)(m & 0x1FFFFFull);
    float fy = (float)((unsigned)(m >> 21) & 0x1FFFu) * (1.0f / 8192.0f);
    float fx = (float)((unsigned)(m >> 34) & 0x1FFFu) * (1.0f / 8192.0f);
    float av = (float)((int)((unsigned)(m >> 47) & 0x1FFFFu) - 65536)
               * (1.0f / 32768.0f);
    const float* gp = gin + idx;
    float f00 = gp[0];
    float f01 = gp[1];
    float f10 = gp[WP];
    float f11 = gp[WP + 1];
    float top = fmaf(fx, f01 - f00, f00);
    float bot = fmaf(fx, f11 - f10, f10);
    acc  = fmaf(av, fmaf(fy, bot - top, top), acc);
    asum += av;
}

__global__ void iter_kernel(const float* __restrict__ conf,
                            float* __restrict__ out, int sel, int last) {
    int t  = blockIdx.x * blockDim.x + threadIdx.x;
    int p0 = 2 * t;
    if (p0 >= NPX) return;
    const float* __restrict__ gin = g_buf[sel];
    int b = p0 / HW;
    int r = p0 - b * HW;
    int y = r / W;
    int x = r - y * W;   // x even; x+1 same row
    int center = (b * HP + y + PAD) * WP + (x + PAD);

    // Front-batched meta loads: 8 x LDG.128, streaming (evict-first) so the
    // 110MB/iter meta stream doesn't evict L2-resident feat/conf.
    uint4 m[8];
#pragma unroll
    for (int q = 0; q < 4; q++) {
        m[2 * q]     = __ldcs(&d_meta[q * NPX + p0]);
        m[2 * q + 1] = __ldcs(&d_meta[q * NPX + p0 + 1]);
    }

    float acc0 = 0.0f, as0 = 0.0f;
    float acc1 = 0.0f, as1 = 0.0f;
#pragma unroll
    for (int q = 0; q < 4; q++) {
        apply_tap(gin, m[2 * q].x,     m[2 * q].y,     acc0, as0);
        apply_tap(gin, m[2 * q].z,     m[2 * q].w,     acc0, as0);
        apply_tap(gin, m[2 * q + 1].x, m[2 * q + 1].y, acc1, as1);
        apply_tap(gin, m[2 * q + 1].z, m[2 * q + 1].w, acc1, as1);
    }
    float v0 = fmaf(1.0f - as0, gin[center],     acc0);
    float v1 = fmaf(1.0f - as1, gin[center + 1], acc1);
    if (last) {
        out[p0]     = v0;
        out[p0 + 1] = v1;
    } else {
        float* gout = g_buf[sel ^ 1];
        gout[center]     = conf[p0]     * v0;
        gout[center + 1] = conf[p0 + 1] * v1;
    }
}

// ---------------------------------------------------------------------------
extern "C" void kernel_launch(void* const* d_in, const int* in_sizes, int n_in,
                              void* d_out, int out_size) {
    const float* feat = (const float*)d_in[0];
    const float* guid = (const float*)d_in[1];
    const float* conf = (const float*)d_in[2];
    const float* w    = (const float*)d_in[3];
    const float* bia  = (const float*)d_in[4];
    const float* sc   = (const float*)d_in[5];
    float* out = (float*)d_out;

    const int thr = 256;
    zero_kernel<<<(2 * NPAD + thr - 1) / thr, thr>>>();
    init_kernel<<<(NPX + thr - 1) / thr, thr>>>(feat, conf);
    conv_meta_kernel<<<(NPX / 2 + thr - 1) / thr, thr>>>(guid, w, bia, sc);
    for (int t = 0; t < PROP; t++) {
        iter_kernel<<<(NPX / 2 + thr - 1) / thr, thr>>>(conf, out, t & 1, t == PROP - 1);
    }
}

// round 11
// speedup vs baseline: 1.2090x; 1.1697x over previous
#include <cuda_runtime.h>
#include <cuda_bf16.h>
#include <stdint.h>

// Problem constants
#define BB   4
#define H    352
#define W    1216
#define HW   (H*W)               // 428032
#define NPX  (BB*HW)             // 1712128 pixels (divisible by 4)
#define PAD  2
#define HP   (H + 2*PAD)         // 356
#define WP   (W + 2*PAD)         // 1220
#define NPAD (BB*HP*WP)          // 1737280 < 2^21
#define PROP 18

typedef unsigned long long u64;

// Packed tap record (u64):
//  [0,21)   : padded linear index of top-left corner
//  [21,34)  : fy  (13-bit fraction, /8192)
//  [34,47)  : fx  (13-bit fraction, /8192)
//  [47,64)  : aff (17-bit fixed point, (q-65536)/32768)
// Stored as 4 planes of uint4 (two taps per 16B record) for LDG.128.

__device__ float g_buf[2][NPAD];          // scalar padded ping-pong feat (conf-folded)
__device__ uint4 d_meta[4 * NPX];

// ---------------------------------------------------------------------------
// Packed fp32x2 helpers (Blackwell dual-rate fp32 path; FFMA2 only via PTX)
__device__ __forceinline__ u64 pack2(float lo, float hi) {
    u64 r; asm("mov.b64 %0, {%1, %2};" : "=l"(r) : "f"(lo), "f"(hi)); return r;
}
__device__ __forceinline__ void unpack2(u64 v, float& lo, float& hi) {
    asm("mov.b64 {%0, %1}, %2;" : "=f"(lo), "=f"(hi) : "l"(v));
}
__device__ __forceinline__ u64 fma2(u64 a, u64 b, u64 c) {
    u64 d; asm("fma.rn.f32x2 %0, %1, %2, %3;" : "=l"(d) : "l"(a), "l"(b), "l"(c));
    return d;
}

// ---------------------------------------------------------------------------
__global__ void zero_kernel() {
    int i = blockIdx.x * blockDim.x + threadIdx.x;
    if (i < 2 * NPAD) (&g_buf[0][0])[i] = 0.0f;
}

__global__ void init_kernel(const float* __restrict__ feat,
                            const float* __restrict__ conf) {
    int p = blockIdx.x * blockDim.x + threadIdx.x;
    if (p >= NPX) return;
    int b = p / HW;
    int r = p - b * HW;
    int y = r / W;
    int x = r - y * W;
    int pidx = (b * HP + y + PAD) * WP + (x + PAD);
    g_buf[0][pidx] = feat[p] * conf[p];
}

// ---------------------------------------------------------------------------
__device__ __forceinline__ unsigned long long encode_tap(
        int b, int y, int x, int j, float dy, float dx, float aff)
{
    float ys = (float)(y + j / 3 - 1) + dy;
    float xs = (float)(x + j % 3 - 1) + dx;
    float y0f = floorf(ys);
    float x0f = floorf(xs);
    float fy = ys - y0f;
    float fx = xs - x0f;
    int iy = (int)fmaxf(fminf(y0f, 1.0e6f), -1.0e6f);
    int ix = (int)fmaxf(fminf(x0f, 1.0e6f), -1.0e6f);
    // clamp into padded box; out-of-image corners land on guaranteed zeros
    int yp = min(max(iy + PAD, 0), HP - 2);
    int xp = min(max(ix + PAD, 0), WP - 2);
    unsigned long long idx = (unsigned long long)((b * HP + yp) * WP + xp);
    int fu = (int)(fy * 8192.0f + 0.5f); fu = min(max(fu, 0), 8191);
    int fv = (int)(fx * 8192.0f + 0.5f); fv = min(max(fv, 0), 8191);
    int qa = (int)floorf(aff * 32768.0f + 0.5f) + 65536;
    qa = min(max(qa, 0), 131071);
    return idx | ((unsigned long long)fu << 21)
               | ((unsigned long long)fv << 34)
               | ((unsigned long long)qa << 47);
}

__device__ __forceinline__ void write_meta(int p, int b, int y, int x,
                                           const float* acc, float inv_scale) {
    float a[8];
    float s = 0.0f;
#pragma unroll
    for (int k = 0; k < 8; k++) {
        a[k] = tanhf(acc[16 + k]) * inv_scale;
        s += fabsf(a[k]);
    }
    s += 1e-4f;
    if (s < 1.0f) s = 1.0f;
    float invs = 1.0f / s;
#pragma unroll
    for (int k = 0; k < 8; k++) a[k] *= invs;

    unsigned long long rec[8];
#pragma unroll
    for (int j = 0; j < 9; j++) {
        if (j == 4) continue;
        int k = (j < 4) ? j : j - 1;
        rec[k] = encode_tap(b, y, x, j, acc[2 * k], acc[2 * k + 1], a[k]);
    }
#pragma unroll
    for (int q = 0; q < 4; q++) {
        unsigned long long m0 = rec[2 * q], m1 = rec[2 * q + 1];
        d_meta[q * NPX + p] = make_uint4((unsigned)m0, (unsigned)(m0 >> 32),
                                         (unsigned)m1, (unsigned)(m1 >> 32));
    }
}

// Conv(8 -> 24, 3x3, pad 1) via packed f32x2 FFMA2; 4 pixels / thread
// (two pixel-pairs). Weights pre-duplicated (w,w) in smem -> LDS.64 broadcast.
__global__ __launch_bounds__(128)
void conv_meta_kernel(const float* __restrict__ guid,
                      const float* __restrict__ w_oa,
                      const float* __restrict__ b_oa,
                      const float* __restrict__ aff_scale) {
    __shared__ u64   ws2[1728];
    __shared__ float bs[24];
    for (int i = threadIdx.x; i < 1728; i += blockDim.x) {
        float w = w_oa[i];
        ws2[i] = pack2(w, w);
    }
    if (threadIdx.x < 24) bs[threadIdx.x] = b_oa[threadIdx.x];
    __syncthreads();

    int t  = blockIdx.x * blockDim.x + threadIdx.x;
    int p0 = 4 * t;
    if (p0 >= NPX) return;
    int b = p0 / HW;
    int r = p0 - b * HW;
    int y = r / W;
    int x = r - y * W;   // x % 4 == 0 (W divisible by 4): 4 px in same row

    u64 accA[24], accB[24];   // accA = (px0,px1), accB = (px2,px3)
#pragma unroll
    for (int c = 0; c < 24; c++) {
        u64 bb2 = pack2(bs[c], bs[c]);
        accA[c] = bb2;
        accB[c] = bb2;
    }

    const float* gb = guid + (size_t)b * 8 * HW;
    for (int i = 0; i < 8; i++) {
        const float* gch = gb + i * HW;
#pragma unroll
        for (int u = 0; u < 3; u++) {
            int yy = y + u - 1;
            bool yv = (yy >= 0) && (yy < H);
            const float* grow = gch + yy * W;
            float v[6];
#pragma unroll
            for (int q = 0; q < 6; q++) {
                int xx = x + q - 1;
                v[q] = (yv && xx >= 0 && xx < W) ? grow[xx] : 0.0f;
            }
#pragma unroll
            for (int kx = 0; kx < 3; kx++) {
                u64 vA = pack2(v[kx],     v[kx + 1]);
                u64 vB = pack2(v[kx + 2], v[kx + 3]);
                const u64* wrow = &ws2[i * 9 + u * 3 + kx];
#pragma unroll
                for (int c = 0; c < 24; c++) {
                    u64 w2 = wrow[c * 72];
                    accA[c] = fma2(vA, w2, accA[c]);
                    accB[c] = fma2(vB, w2, accB[c]);
                }
            }
        }
    }

    float inv_scale = 1.0f / (aff_scale[0] + 1e-8f);
    float tmp0[24], tmp1[24];
#pragma unroll
    for (int c = 0; c < 24; c++) unpack2(accA[c], tmp0[c], tmp1[c]);
    write_meta(p0,     b, y, x,     tmp0, inv_scale);
    write_meta(p0 + 1, b, y, x + 1, tmp1, inv_scale);
#pragma unroll
    for (int c = 0; c < 24; c++) unpack2(accB[c], tmp0[c], tmp1[c]);
    write_meta(p0 + 2, b, y, x + 2, tmp0, inv_scale);
    write_meta(p0 + 3, b, y, x + 3, tmp1, inv_scale);
}

// ---------------------------------------------------------------------------
// One propagation step (R5 shape: 1 px/thread, scalar gathers, plain loads).
// Center affinity = 1 - sum(decoded tap affs): operator rows sum exactly to 1.
__device__ __forceinline__ void apply_tap(const float* __restrict__ gin,
                                          unsigned lo, unsigned hi,
                                          float& acc, float& asum) {
    unsigned long long m = (unsigned long long)lo
                         | ((unsigned long long)hi << 32);
    unsigned idx = (unsigned)(m & 0x1FFFFFull);
    float fy = (float)((unsigned)(m >> 21) & 0x1FFFu) * (1.0f / 8192.0f);
    float fx = (float)((unsigned)(m >> 34) & 0x1FFFu) * (1.0f / 8192.0f);
    float av = (float)((int)((unsigned)(m >> 47) & 0x1FFFFu) - 65536)
               * (1.0f / 32768.0f);
    const float* gp = gin + idx;
    float f00 = gp[0];
    float f01 = gp[1];
    float f10 = gp[WP];
    float f11 = gp[WP + 1];
    float top = fmaf(fx, f01 - f00, f00);
    float bot = fmaf(fx, f11 - f10, f10);
    acc  = fmaf(av, fmaf(fy, bot - top, top), acc);
    asum += av;
}

__global__ void iter_kernel(const float* __restrict__ conf,
                            float* __restrict__ out, int sel, int last) {
    int p = blockIdx.x * blockDim.x + threadIdx.x;
    if (p >= NPX) return;
    const float* __restrict__ gin = g_buf[sel];
    int b = p / HW;
    int r = p - b * HW;
    int y = r / W;
    int x = r - y * W;
    int center = (b * HP + y + PAD) * WP + (x + PAD);

    float acc = 0.0f, asum = 0.0f;
#pragma unroll
    for (int q = 0; q < 4; q++) {
        uint4 mm = d_meta[q * NPX + p];
        apply_tap(gin, mm.x, mm.y, acc, asum);
        apply_tap(gin, mm.z, mm.w, acc, asum);
    }
    float v = fmaf(1.0f - asum, gin[center], acc);
    if (last) out[p] = v;
    else      g_buf[sel ^ 1][center] = conf[p] * v;
}

// ---------------------------------------------------------------------------
extern "C" void kernel_launch(void* const* d_in, const int* in_sizes, int n_in,
                              void* d_out, int out_size) {
    const float* feat = (const float*)d_in[0];
    const float* guid = (const float*)d_in[1];
    const float* conf = (const float*)d_in[2];
    const float* w    = (const float*)d_in[3];
    const float* bia  = (const float*)d_in[4];
    const float* sc   = (const float*)d_in[5];
    float* out = (float*)d_out;

    const int thr = 256;
    zero_kernel<<<(2 * NPAD + thr - 1) / thr, thr>>>();
    init_kernel<<<(NPX + thr - 1) / thr, thr>>>(feat, conf);
    conv_meta_kernel<<<(NPX / 4 + 127) / 128, 128>>>(guid, w, bia, sc);
    for (int t = 0; t < PROP; t++) {
        iter_kernel<<<(NPX + thr - 1) / thr, thr>>>(conf, out, t & 1, t == PROP - 1);
    }
}